// round 5
// baseline (speedup 1.0000x reference)
#include <cuda_runtime.h>

// Problem constants
#define M_DIM   16
#define DICT    64
#define N_DIM   8
#define B_DIM   8192
#define KTERMS  16
#define BDIM    256

// Grid: (B/256, DICT). Block handles 256 consecutive b for one dictionary slot s.
// Each thread: builds its 8x8 A in registers, evaluates expm(A)*x via a fully
// unrolled 16-term Horner recurrence:  u <- x + (A u)/k,  k = K..1.
__global__ __launch_bounds__(BDIM, 2)
void transop_expm_kernel(const float* __restrict__ x,
                         const float* __restrict__ c,
                         const float* __restrict__ psi,
                         float* __restrict__ out)
{
    const int s = blockIdx.y;                       // dictionary slot
    const int b = blockIdx.x * BDIM + threadIdx.x;  // batch element

    // psi[m, s, :, :] slice: 16 m-rows x 64 entries = 1024 floats = 256 float4.
    __shared__ float4 psi_s[M_DIM * 16];
    {
        const int t = threadIdx.x;
        const int m = t >> 4;        // 0..15
        const int q = t & 15;        // 0..15 (float4 within the 64-entry tile)
        psi_s[t] = reinterpret_cast<const float4*>(psi)[(m * DICT + s) * 16 + q];
    }

    // Overlap global loads with the smem staging (before the barrier).
    // c[b, :] — 16 contiguous floats.
    float4 c0, c1, c2, c3;
    {
        const float4* c4 = reinterpret_cast<const float4*>(c + (size_t)b * M_DIM);
        c0 = c4[0]; c1 = c4[1]; c2 = c4[2]; c3 = c4[3];
    }
    // x block: x[b, s*8 .. s*8+8) — contiguous 32B per thread.
    float xv[N_DIM];
    {
        const float4* xp = reinterpret_cast<const float4*>(
            x + (size_t)b * (DICT * N_DIM) + s * N_DIM);
        float4 x0 = xp[0], x1 = xp[1];
        xv[0] = x0.x; xv[1] = x0.y; xv[2] = x0.z; xv[3] = x0.w;
        xv[4] = x1.x; xv[5] = x1.y; xv[6] = x1.z; xv[7] = x1.w;
    }

    __syncthreads();

    float cm[M_DIM];
    cm[0] = c0.x; cm[1] = c0.y; cm[2]  = c0.z; cm[3]  = c0.w;
    cm[4] = c1.x; cm[5] = c1.y; cm[6]  = c1.z; cm[7]  = c1.w;
    cm[8] = c2.x; cm[9] = c2.y; cm[10] = c2.z; cm[11] = c2.w;
    cm[12]= c3.x; cm[13]= c3.y; cm[14] = c3.z; cm[15] = c3.w;

    // Build A[n*8+j] = sum_m cm[m] * psi_s[m][nj]   (broadcast LDS.128)
    float A[64];
    #pragma unroll
    for (int i = 0; i < 64; i++) A[i] = 0.0f;

    #pragma unroll
    for (int m = 0; m < M_DIM; m++) {
        const float cv = cm[m];
        #pragma unroll
        for (int q = 0; q < 16; q++) {
            float4 p = psi_s[m * 16 + q];
            A[4 * q + 0] = fmaf(cv, p.x, A[4 * q + 0]);
            A[4 * q + 1] = fmaf(cv, p.y, A[4 * q + 1]);
            A[4 * q + 2] = fmaf(cv, p.z, A[4 * q + 2]);
            A[4 * q + 3] = fmaf(cv, p.w, A[4 * q + 3]);
        }
    }

    // Horner:  u = x;  for k = K..1:  u <- x + (A u)/k.
    // 1/k are compile-time immediates (FFMA-imm), no constant loads, no copies.
    float u[N_DIM];
    #pragma unroll
    for (int i = 0; i < N_DIM; i++) u[i] = xv[i];

    #pragma unroll
    for (int k = KTERMS; k >= 1; k--) {
        const float ik = 1.0f / (float)k;   // compile-time constant
        float t[N_DIM];
        #pragma unroll
        for (int n = 0; n < N_DIM; n++) {
            float sum = A[n * 8 + 0] * u[0];
            #pragma unroll
            for (int j = 1; j < N_DIM; j++)
                sum = fmaf(A[n * 8 + j], u[j], sum);
            t[n] = sum;
        }
        #pragma unroll
        for (int i = 0; i < N_DIM; i++)
            u[i] = fmaf(ik, t[i], xv[i]);
    }

    // Store out[b, s*8 .. s*8+8)
    {
        float4* op = reinterpret_cast<float4*>(
            out + (size_t)b * (DICT * N_DIM) + s * N_DIM);
        op[0] = make_float4(u[0], u[1], u[2], u[3]);
        op[1] = make_float4(u[4], u[5], u[6], u[7]);
    }
}

extern "C" void kernel_launch(void* const* d_in, const int* in_sizes, int n_in,
                              void* d_out, int out_size)
{
    const float* x   = (const float*)d_in[0];  // (8192, 512)
    const float* c   = (const float*)d_in[1];  // (8192, 16)
    const float* psi = (const float*)d_in[2];  // (16, 64, 8, 8)
    float* out = (float*)d_out;                // (8192, 512)

    dim3 grid(B_DIM / BDIM, DICT);
    transop_expm_kernel<<<grid, BDIM>>>(x, c, psi, out);
}

// round 6
// speedup vs baseline: 1.5809x; 1.5809x over previous
#include <cuda_runtime.h>

// Problem constants
#define M_DIM   16
#define DICT    64
#define N_DIM   8
#define B_DIM   8192
#define KTERMS  16
#define BDIM    256
#define PAIRS_PER_BLK (BDIM / 2)   // 128 matrices per block

// Grid: (B/128, DICT). A lane PAIR (t, t^1) handles one (b, s) matrix:
// lane half h = t&1 owns rows 4h..4h+3 of A (32 regs) and components
// 4h..4h+3 of the state vector. Per Horner step, each lane computes its
// 4 outputs (needs the full 8-vector: 4 own + 4 from partner via shfl.xor).
// A is stored thread-relative: A[rl*8 + slot], slot 0..3 multiply u_mine,
// slot 4..7 multiply u_other — all register indices compile-time; only
// shared/global ADDRESSES depend on h.
__global__ __launch_bounds__(BDIM, 3)
void transop_expm_kernel(const float* __restrict__ x,
                         const float* __restrict__ c,
                         const float* __restrict__ psi,
                         float* __restrict__ out)
{
    const int s = blockIdx.y;
    const int t = threadIdx.x;
    const int p = t >> 1;                 // pair index within block
    const int h = t & 1;                  // which half of the matrix I own
    const int b = blockIdx.x * PAIRS_PER_BLK + p;

    // psi[m, s, :, :] slice: 16 m x 64 floats = 256 float4.
    // Layout: float4 index m*16 + row*2 + colhalf.
    __shared__ float4 psi_s[M_DIM * 16];
    psi_s[t] = reinterpret_cast<const float4*>(psi)[((t >> 4) * DICT + s) * 16 + (t & 15)];

    // Global loads overlapped with staging (before the barrier).
    // c[b, :]: full 16 floats per lane (pair lanes read the same line -> L1 hit).
    float4 c0, c1, c2, c3;
    {
        const float4* c4 = reinterpret_cast<const float4*>(c + (size_t)b * M_DIM);
        c0 = c4[0]; c1 = c4[1]; c2 = c4[2]; c3 = c4[3];
    }
    // My half of x[b, s*8..s*8+8): 4 floats (pair covers 32B contiguous).
    float4 xm4 = *reinterpret_cast<const float4*>(
        x + (size_t)b * (DICT * N_DIM) + s * N_DIM + h * 4);

    __syncthreads();

    float cm[M_DIM];
    cm[0] = c0.x; cm[1] = c0.y; cm[2]  = c0.z; cm[3]  = c0.w;
    cm[4] = c1.x; cm[5] = c1.y; cm[6]  = c1.z; cm[7]  = c1.w;
    cm[8] = c2.x; cm[9] = c2.y; cm[10] = c2.z; cm[11] = c2.w;
    cm[12]= c3.x; cm[13]= c3.y; cm[14] = c3.z; cm[15] = c3.w;

    // Build my 4x8 slab of A, thread-relative column slots.
    //   A[rl*8 + 0..3]  = A_abs[4h+rl][4h   .. 4h+3]   (multiplies u_mine)
    //   A[rl*8 + 4..7]  = A_abs[4h+rl][4(1-h)..4(1-h)+3] (multiplies u_other)
    // psi float4 address for (m, row 4h+rl, colhalf cc): m*16 + (4h+rl)*2 + cc.
    float A[32];
    #pragma unroll
    for (int i = 0; i < 32; i++) A[i] = 0.0f;

    const int rowbase = 8 * h;        // (4h)*2
    const int ccm = h;                // colhalf of my own columns
    const int cco = 1 - h;            // colhalf of partner columns

    #pragma unroll
    for (int m = 0; m < M_DIM; m++) {
        const float cv = cm[m];
        #pragma unroll
        for (int rl = 0; rl < 4; rl++) {
            float4 pm = psi_s[m * 16 + rowbase + rl * 2 + ccm];
            float4 po = psi_s[m * 16 + rowbase + rl * 2 + cco];
            A[rl * 8 + 0] = fmaf(cv, pm.x, A[rl * 8 + 0]);
            A[rl * 8 + 1] = fmaf(cv, pm.y, A[rl * 8 + 1]);
            A[rl * 8 + 2] = fmaf(cv, pm.z, A[rl * 8 + 2]);
            A[rl * 8 + 3] = fmaf(cv, pm.w, A[rl * 8 + 3]);
            A[rl * 8 + 4] = fmaf(cv, po.x, A[rl * 8 + 4]);
            A[rl * 8 + 5] = fmaf(cv, po.y, A[rl * 8 + 5]);
            A[rl * 8 + 6] = fmaf(cv, po.z, A[rl * 8 + 6]);
            A[rl * 8 + 7] = fmaf(cv, po.w, A[rl * 8 + 7]);
        }
    }

    // State: u_mine = my 4 components, u_other = partner's 4 (kept in sync by shfl).
    float xm[4] = {xm4.x, xm4.y, xm4.z, xm4.w};
    float um[4], uo[4];
    #pragma unroll
    for (int i = 0; i < 4; i++) {
        um[i] = xm[i];
        uo[i] = __shfl_xor_sync(0xffffffffu, xm[i], 1);
    }

    // Horner: u <- x + (A u)/k, k = K..1.  1/k are FFMA immediates.
    #pragma unroll
    for (int k = KTERMS; k >= 1; k--) {
        const float ik = 1.0f / (float)k;
        float tl[4];
        #pragma unroll
        for (int rl = 0; rl < 4; rl++) {
            float sum = A[rl * 8 + 0] * um[0];
            sum = fmaf(A[rl * 8 + 1], um[1], sum);
            sum = fmaf(A[rl * 8 + 2], um[2], sum);
            sum = fmaf(A[rl * 8 + 3], um[3], sum);
            sum = fmaf(A[rl * 8 + 4], uo[0], sum);
            sum = fmaf(A[rl * 8 + 5], uo[1], sum);
            sum = fmaf(A[rl * 8 + 6], uo[2], sum);
            sum = fmaf(A[rl * 8 + 7], uo[3], sum);
            tl[rl] = sum;
        }
        #pragma unroll
        for (int i = 0; i < 4; i++)
            um[i] = fmaf(ik, tl[i], xm[i]);
        #pragma unroll
        for (int i = 0; i < 4; i++)
            uo[i] = __shfl_xor_sync(0xffffffffu, um[i], 1);
    }

    // Store my half: pair writes 32B contiguous.
    *reinterpret_cast<float4*>(out + (size_t)b * (DICT * N_DIM) + s * N_DIM + h * 4)
        = make_float4(um[0], um[1], um[2], um[3]);
}

extern "C" void kernel_launch(void* const* d_in, const int* in_sizes, int n_in,
                              void* d_out, int out_size)
{
    const float* x   = (const float*)d_in[0];  // (8192, 512)
    const float* c   = (const float*)d_in[1];  // (8192, 16)
    const float* psi = (const float*)d_in[2];  // (16, 64, 8, 8)
    float* out = (float*)d_out;                // (8192, 512)

    dim3 grid(B_DIM / PAIRS_PER_BLK, DICT);
    transop_expm_kernel<<<grid, BDIM>>>(x, c, psi, out);
}

// round 8
// speedup vs baseline: 1.5869x; 1.0037x over previous
#include <cuda_runtime.h>

// Problem constants
#define M_DIM   16
#define DICT    64
#define N_DIM   8
#define B_DIM   8192
#define KTERMS  16
#define BDIM    256
#define NB      128              // b-values per block
#define A_STRIDE 68              // padded float stride of one A matrix in smem
#define CT_STRIDE 132            // padded float stride of one cT row (b-dim)

// Grid: (B/128, DICT).
// Phase 1: cooperative A-build. Block computes A[b][nk] for 128 b x 64 nk
//   as a (128x16)@(16x64) mini-GEMM with 8-way b-reuse per psi load:
//   thread (o = b-octet, g = nk-quad) computes 8b x 4nk entries.
// Phase 2: pair-split Horner: lanes (t, t^1) split one matrix. Lane half h
//   owns rows 4h..4h+3; register slots 0..3 hold MY columns (4h..4h+3,
//   multiplying um), slots 4..7 hold PARTNER columns (multiplying uo).
//   NOTE: A_s is absolute-column order, so the two column quads are loaded
//   from offsets 4h (mine) and 4(1-h) (partner) — this was the R7 bug.
__global__ __launch_bounds__(BDIM, 3)
void transop_expm_kernel(const float* __restrict__ x,
                         const float* __restrict__ c,
                         const float* __restrict__ psi,
                         float* __restrict__ out)
{
    const int s   = blockIdx.y;
    const int tid = threadIdx.x;
    const int b0  = blockIdx.x * NB;

    __shared__ float4 psi_s[M_DIM * 16];          //  4 KB: psi[m,s,:,:]
    __shared__ float  cT[M_DIM * CT_STRIDE];      //  8.25 KB: cT[m][b_loc]
    __shared__ float  A_s[NB * A_STRIDE];         // 34 KB: A[b_loc][nk] (pad 4)

    // ---- Stage psi slice (256 float4) and c transposed ----
    psi_s[tid] = reinterpret_cast<const float4*>(psi)[((tid >> 4) * DICT + s) * 16 + (tid & 15)];

    {
        // c[b0 .. b0+127][0..15] = 512 float4, 2 per thread, coalesced.
        const float4* cg = reinterpret_cast<const float4*>(c) + (size_t)b0 * 4;
        #pragma unroll
        for (int u = 0; u < 2; u++) {
            int i = tid + u * BDIM;           // 0..511
            float4 v = cg[i];
            int b_loc = i >> 2;               // 0..127
            int mb    = (i & 3) * 4;          // m base
            cT[(mb + 0) * CT_STRIDE + b_loc] = v.x;
            cT[(mb + 1) * CT_STRIDE + b_loc] = v.y;
            cT[(mb + 2) * CT_STRIDE + b_loc] = v.z;
            cT[(mb + 3) * CT_STRIDE + b_loc] = v.w;
        }
    }
    __syncthreads();

    // ---- Phase 1: A-build, 8 b x 4 nk per thread ----
    {
        const int g = tid & 15;               // nk-quad: nk = 4g..4g+3
        const int o = tid >> 4;               // b-octet: b_loc = 8o..8o+7

        float4 acc[8];
        #pragma unroll
        for (int i = 0; i < 8; i++) acc[i] = make_float4(0.f, 0.f, 0.f, 0.f);

        #pragma unroll
        for (int m = 0; m < M_DIM; m++) {
            float4 pg = psi_s[m * 16 + g];
            float4 ca = *reinterpret_cast<const float4*>(&cT[m * CT_STRIDE + 8 * o]);
            float4 cb = *reinterpret_cast<const float4*>(&cT[m * CT_STRIDE + 8 * o + 4]);
            float cv[8] = {ca.x, ca.y, ca.z, ca.w, cb.x, cb.y, cb.z, cb.w};
            #pragma unroll
            for (int bi = 0; bi < 8; bi++) {
                acc[bi].x = fmaf(cv[bi], pg.x, acc[bi].x);
                acc[bi].y = fmaf(cv[bi], pg.y, acc[bi].y);
                acc[bi].z = fmaf(cv[bi], pg.z, acc[bi].z);
                acc[bi].w = fmaf(cv[bi], pg.w, acc[bi].w);
            }
        }

        #pragma unroll
        for (int bi = 0; bi < 8; bi++) {
            int b_loc = 8 * o + bi;
            *reinterpret_cast<float4*>(&A_s[b_loc * A_STRIDE + 4 * g]) = acc[bi];
        }
    }
    __syncthreads();

    // ---- Phase 2: pair-split Horner ----
    const int p = tid >> 1;                   // matrix index in block (b_loc)
    const int h = tid & 1;                    // half: rows 4h..4h+3
    const int b = b0 + p;

    // Read my 4x8 slab of A from smem, converting absolute columns to
    // thread-relative slots: slots 0..3 = my columns (4h..), slots 4..7 =
    // partner columns (4(1-h)..).
    const int myc = 4 * h;                    // my column quad offset
    const int otc = 4 * (1 - h);              // partner column quad offset
    float A[4][8];
    #pragma unroll
    for (int rl = 0; rl < 4; rl++) {
        int r = 4 * h + rl;
        float4 a0 = *reinterpret_cast<const float4*>(&A_s[p * A_STRIDE + r * 8 + myc]);
        float4 a1 = *reinterpret_cast<const float4*>(&A_s[p * A_STRIDE + r * 8 + otc]);
        A[rl][0] = a0.x; A[rl][1] = a0.y; A[rl][2] = a0.z; A[rl][3] = a0.w;
        A[rl][4] = a1.x; A[rl][5] = a1.y; A[rl][6] = a1.z; A[rl][7] = a1.w;
    }

    // My half of x[b, s*8..s*8+8).
    float4 xm4 = *reinterpret_cast<const float4*>(
        x + (size_t)b * (DICT * N_DIM) + s * N_DIM + h * 4);
    float xm[4] = {xm4.x, xm4.y, xm4.z, xm4.w};

    float um[4], uo[4];
    #pragma unroll
    for (int i = 0; i < 4; i++) {
        um[i] = xm[i];
        uo[i] = __shfl_xor_sync(0xffffffffu, xm[i], 1);
    }

    // Horner: u <- x + (A u)/k, k = K..1. 1/k are FFMA immediates.
    #pragma unroll
    for (int k = KTERMS; k >= 1; k--) {
        const float ik = 1.0f / (float)k;
        float tl[4];
        #pragma unroll
        for (int rl = 0; rl < 4; rl++) {
            float sum = A[rl][0] * um[0];
            sum = fmaf(A[rl][1], um[1], sum);
            sum = fmaf(A[rl][2], um[2], sum);
            sum = fmaf(A[rl][3], um[3], sum);
            sum = fmaf(A[rl][4], uo[0], sum);
            sum = fmaf(A[rl][5], uo[1], sum);
            sum = fmaf(A[rl][6], uo[2], sum);
            sum = fmaf(A[rl][7], uo[3], sum);
            tl[rl] = sum;
        }
        #pragma unroll
        for (int i = 0; i < 4; i++)
            um[i] = fmaf(ik, tl[i], xm[i]);
        #pragma unroll
        for (int i = 0; i < 4; i++)
            uo[i] = __shfl_xor_sync(0xffffffffu, um[i], 1);
    }

    // Store my half: pair writes 32B contiguous.
    *reinterpret_cast<float4*>(out + (size_t)b * (DICT * N_DIM) + s * N_DIM + h * 4)
        = make_float4(um[0], um[1], um[2], um[3]);
}

extern "C" void kernel_launch(void* const* d_in, const int* in_sizes, int n_in,
                              void* d_out, int out_size)
{
    const float* x   = (const float*)d_in[0];  // (8192, 512)
    const float* c   = (const float*)d_in[1];  // (8192, 16)
    const float* psi = (const float*)d_in[2];  // (16, 64, 8, 8)
    float* out = (float*)d_out;                // (8192, 512)

    dim3 grid(B_DIM / NB, DICT);
    transop_expm_kernel<<<grid, BDIM>>>(x, c, psi, out);
}

// round 10
// speedup vs baseline: 1.6110x; 1.0152x over previous
#include <cuda_runtime.h>

// Problem constants
#define M_DIM   16
#define DICT    64
#define N_DIM   8
#define B_DIM   8192
#define KTERMS  16
#define BDIM    128
#define NB      128              // matrices (b-values) per block
#define A_STRIDE 68              // padded float stride of one A matrix in smem
#define CT_STRIDE 132            // padded float stride of one cT row (b-dim)

// 1/k table, k=0 unused (rolled Horner loop -> LDC, keeps reg pressure low)
__device__ __constant__ float INVK[KTERMS + 1] = {
    0.0f,
    1.0f/1,  1.0f/2,  1.0f/3,  1.0f/4,  1.0f/5,  1.0f/6,  1.0f/7,  1.0f/8,
    1.0f/9,  1.0f/10, 1.0f/11, 1.0f/12, 1.0f/13, 1.0f/14, 1.0f/15, 1.0f/16
};

// Grid: (B/128, DICT). Block = 128 threads, 128 matrices.
// Phase 1 (cooperative A-build): thread (o = b-octet, g = nk-octet) computes
//   an 8b x 8nk tile of A = c @ psi[:,s]: per m just 2 psi float4 + 2 cT
//   float4 feed 64 FMAs (2x the arithmetic intensity of the 8x4 tiling).
// Phase 2 (no exchange): thread p owns matrix p end-to-end: 16 conflict-free
//   LDS.128 pull its A, then a rolled 16-step Horner u <- x + (A u)/k runs
//   entirely in registers. Zero SHFL.
__global__ __launch_bounds__(BDIM, 4)
void transop_expm_kernel(const float* __restrict__ x,
                         const float* __restrict__ c,
                         const float* __restrict__ psi,
                         float* __restrict__ out)
{
    const int s   = blockIdx.y;
    const int tid = threadIdx.x;
    const int b0  = blockIdx.x * NB;

    __shared__ float4 psi_s[M_DIM * 16];          //  4 KB   psi[m,s,:,:]
    __shared__ float  cT[M_DIM * CT_STRIDE];      //  8.25 KB cT[m][b_loc]
    __shared__ float  A_s[NB * A_STRIDE];         // 34 KB   A[b_loc][nk]

    // ---- Stage psi slice (256 float4, 2/thread) ----
    #pragma unroll
    for (int u = 0; u < 2; u++) {
        int i = tid + u * BDIM;      // 0..255
        psi_s[i] = reinterpret_cast<const float4*>(psi)[((i >> 4) * DICT + s) * 16 + (i & 15)];
    }

    // ---- Stage c transposed: c[b0..b0+127][0..15] = 512 float4, 4/thread ----
    {
        const float4* cg = reinterpret_cast<const float4*>(c) + (size_t)b0 * 4;
        #pragma unroll
        for (int u = 0; u < 4; u++) {
            int i = tid + u * BDIM;           // 0..511
            float4 v = cg[i];
            int b_loc = i >> 2;               // 0..127
            int mb    = (i & 3) * 4;          // m base
            cT[(mb + 0) * CT_STRIDE + b_loc] = v.x;
            cT[(mb + 1) * CT_STRIDE + b_loc] = v.y;
            cT[(mb + 2) * CT_STRIDE + b_loc] = v.z;
            cT[(mb + 3) * CT_STRIDE + b_loc] = v.w;
        }
    }
    __syncthreads();

    // ---- Phase 1: A-build, 8 b x 8 nk per thread ----
    {
        const int g = tid & 7;                // nk-octet: nk = 8g..8g+7
        const int o = tid >> 3;               // b-octet: b_loc = 8o..8o+7

        float4 acc[16];                       // [bi*2 + j]: rows bi, nk half j
        #pragma unroll
        for (int i = 0; i < 16; i++) acc[i] = make_float4(0.f, 0.f, 0.f, 0.f);

        #pragma unroll
        for (int m = 0; m < M_DIM; m++) {
            float4 p0 = psi_s[m * 16 + 2 * g];
            float4 p1 = psi_s[m * 16 + 2 * g + 1];
            float4 ca = *reinterpret_cast<const float4*>(&cT[m * CT_STRIDE + 8 * o]);
            float4 cb = *reinterpret_cast<const float4*>(&cT[m * CT_STRIDE + 8 * o + 4]);
            float cv[8] = {ca.x, ca.y, ca.z, ca.w, cb.x, cb.y, cb.z, cb.w};
            #pragma unroll
            for (int bi = 0; bi < 8; bi++) {
                acc[bi*2  ].x = fmaf(cv[bi], p0.x, acc[bi*2  ].x);
                acc[bi*2  ].y = fmaf(cv[bi], p0.y, acc[bi*2  ].y);
                acc[bi*2  ].z = fmaf(cv[bi], p0.z, acc[bi*2  ].z);
                acc[bi*2  ].w = fmaf(cv[bi], p0.w, acc[bi*2  ].w);
                acc[bi*2+1].x = fmaf(cv[bi], p1.x, acc[bi*2+1].x);
                acc[bi*2+1].y = fmaf(cv[bi], p1.y, acc[bi*2+1].y);
                acc[bi*2+1].z = fmaf(cv[bi], p1.z, acc[bi*2+1].z);
                acc[bi*2+1].w = fmaf(cv[bi], p1.w, acc[bi*2+1].w);
            }
        }

        #pragma unroll
        for (int bi = 0; bi < 8; bi++) {
            int b_loc = 8 * o + bi;
            *reinterpret_cast<float4*>(&A_s[b_loc * A_STRIDE + 8 * g])     = acc[bi*2];
            *reinterpret_cast<float4*>(&A_s[b_loc * A_STRIDE + 8 * g + 4]) = acc[bi*2+1];
        }
    }
    __syncthreads();

    // ---- Phase 2: one matrix per thread, register Horner, no exchange ----
    const int p = tid;
    const int b = b0 + p;

    // Pull my 8x8 A (16 LDS.128; stride 68 floats -> bank = 4p+q, conflict-free).
    float A[64];
    #pragma unroll
    for (int r = 0; r < 8; r++) {
        float4 a0 = *reinterpret_cast<const float4*>(&A_s[p * A_STRIDE + 8 * r]);
        float4 a1 = *reinterpret_cast<const float4*>(&A_s[p * A_STRIDE + 8 * r + 4]);
        A[8*r+0] = a0.x; A[8*r+1] = a0.y; A[8*r+2] = a0.z; A[8*r+3] = a0.w;
        A[8*r+4] = a1.x; A[8*r+5] = a1.y; A[8*r+6] = a1.z; A[8*r+7] = a1.w;
    }

    // x[b, s*8 .. s*8+8)
    float xv[N_DIM], u[N_DIM];
    {
        const float4* xp = reinterpret_cast<const float4*>(
            x + (size_t)b * (DICT * N_DIM) + s * N_DIM);
        float4 x0 = xp[0], x1 = xp[1];
        xv[0] = x0.x; xv[1] = x0.y; xv[2] = x0.z; xv[3] = x0.w;
        xv[4] = x1.x; xv[5] = x1.y; xv[6] = x1.z; xv[7] = x1.w;
        #pragma unroll
        for (int i = 0; i < N_DIM; i++) u[i] = xv[i];
    }

    // Horner: u <- x + (A u)/k, k = K..1 (rolled; 1/k via constant table).
    #pragma unroll 1
    for (int k = KTERMS; k >= 1; k--) {
        const float ik = INVK[k];
        float t[N_DIM];
        #pragma unroll
        for (int n = 0; n < N_DIM; n++) {
            float sum = A[n * 8 + 0] * u[0];
            #pragma unroll
            for (int j = 1; j < N_DIM; j++)
                sum = fmaf(A[n * 8 + j], u[j], sum);
            t[n] = sum;
        }
        #pragma unroll
        for (int i = 0; i < N_DIM; i++)
            u[i] = fmaf(ik, t[i], xv[i]);
    }

    // Store out[b, s*8 .. s*8+8)
    {
        float4* op = reinterpret_cast<float4*>(
            out + (size_t)b * (DICT * N_DIM) + s * N_DIM);
        op[0] = make_float4(u[0], u[1], u[2], u[3]);
        op[1] = make_float4(u[4], u[5], u[6], u[7]);
    }
}

extern "C" void kernel_launch(void* const* d_in, const int* in_sizes, int n_in,
                              void* d_out, int out_size)
{
    const float* x   = (const float*)d_in[0];  // (8192, 512)
    const float* c   = (const float*)d_in[1];  // (8192, 16)
    const float* psi = (const float*)d_in[2];  // (16, 64, 8, 8)
    float* out = (float*)d_out;                // (8192, 512)

    dim3 grid(B_DIM / NB, DICT);
    transop_expm_kernel<<<grid, BDIM>>>(x, c, psi, out);
}

// round 11
// speedup vs baseline: 1.9966x; 1.2394x over previous
#include <cuda_runtime.h>

// Problem constants
#define M_DIM   16
#define DICT    64
#define N_DIM   8
#define B_DIM   8192
#define KTERMS  12
#define BDIM    128
#define NB      128              // matrices (b-values) per block
#define A_STRIDE 68              // padded float stride of one A matrix in smem
#define CT_STRIDE 132            // padded float stride of one cT row (b-dim)
#define PSI_STRIDE 17            // float4 stride of one psi m-row (swizzled)

// 1/k table, k=0 unused (rolled Horner loop -> LDC, keeps reg pressure low)
__device__ __constant__ float INVK[KTERMS + 1] = {
    0.0f,
    1.0f/1,  1.0f/2,  1.0f/3,  1.0f/4,  1.0f/5,  1.0f/6,
    1.0f/7,  1.0f/8,  1.0f/9,  1.0f/10, 1.0f/11, 1.0f/12
};

// Grid: (B/128, DICT). Block = 128 threads, 128 matrices.
//
// Bank-conflict-free smem layouts:
//  psi_s: float4 index m*17 + q + (q>>3).  Loads psi_s[m*17 + 2g + (g>>2)]
//    for g=0..7 hit float-banks {0,8,16,24,4,12,20,28} — all distinct.
//  A_s: matrix row g stored at float offset 8g + 4*(g>>2) (span 68 = stride).
//    Store phase (fixed bi, g=0..7) and read phase (fixed r, p=0..7,
//    68p mod 32 = 4p) are both conflict-free.
__global__ __launch_bounds__(BDIM, 4)
void transop_expm_kernel(const float* __restrict__ x,
                         const float* __restrict__ c,
                         const float* __restrict__ psi,
                         float* __restrict__ out)
{
    const int s   = blockIdx.y;
    const int tid = threadIdx.x;
    const int b0  = blockIdx.x * NB;

    __shared__ float4 psi_s[M_DIM * PSI_STRIDE];  //  4.25 KB  psi[m,s,:,:] (swizzled)
    __shared__ float  cT[M_DIM * CT_STRIDE];      //  8.25 KB  cT[m][b_loc]
    __shared__ float  A_s[NB * A_STRIDE];         // 34 KB     A[b_loc][..] (col-swizzled)

    // ---- Stage psi slice (256 float4, 2/thread), swizzled ----
    #pragma unroll
    for (int u = 0; u < 2; u++) {
        int i = tid + u * BDIM;      // 0..255
        int m = i >> 4;
        int q = i & 15;
        psi_s[m * PSI_STRIDE + q + (q >> 3)] =
            reinterpret_cast<const float4*>(psi)[(m * DICT + s) * 16 + q];
    }

    // ---- Stage c transposed: c[b0..b0+127][0..15] = 512 float4, 4/thread ----
    {
        const float4* cg = reinterpret_cast<const float4*>(c) + (size_t)b0 * 4;
        #pragma unroll
        for (int u = 0; u < 4; u++) {
            int i = tid + u * BDIM;           // 0..511
            float4 v = cg[i];
            int b_loc = i >> 2;               // 0..127
            int mb    = (i & 3) * 4;          // m base
            cT[(mb + 0) * CT_STRIDE + b_loc] = v.x;
            cT[(mb + 1) * CT_STRIDE + b_loc] = v.y;
            cT[(mb + 2) * CT_STRIDE + b_loc] = v.z;
            cT[(mb + 3) * CT_STRIDE + b_loc] = v.w;
        }
    }
    __syncthreads();

    // ---- Phase 1: A-build, 8 b x 8 nk per thread ----
    {
        const int g  = tid & 7;               // matrix row (nk-octet): nk = 8g..8g+7
        const int o  = tid >> 3;              // b-octet: b_loc = 8o..8o+7
        const int og = g >> 2;                // psi/A swizzle offset

        float4 acc[16];                       // [bi*2 + j]: matrices bi, col half j
        #pragma unroll
        for (int i = 0; i < 16; i++) acc[i] = make_float4(0.f, 0.f, 0.f, 0.f);

        #pragma unroll
        for (int m = 0; m < M_DIM; m++) {
            const float4* prow = &psi_s[m * PSI_STRIDE + 2 * g + og];
            float4 p0 = prow[0];
            float4 p1 = prow[1];
            float4 ca = *reinterpret_cast<const float4*>(&cT[m * CT_STRIDE + 8 * o]);
            float4 cb = *reinterpret_cast<const float4*>(&cT[m * CT_STRIDE + 8 * o + 4]);
            float cv[8] = {ca.x, ca.y, ca.z, ca.w, cb.x, cb.y, cb.z, cb.w};
            #pragma unroll
            for (int bi = 0; bi < 8; bi++) {
                acc[bi*2  ].x = fmaf(cv[bi], p0.x, acc[bi*2  ].x);
                acc[bi*2  ].y = fmaf(cv[bi], p0.y, acc[bi*2  ].y);
                acc[bi*2  ].z = fmaf(cv[bi], p0.z, acc[bi*2  ].z);
                acc[bi*2  ].w = fmaf(cv[bi], p0.w, acc[bi*2  ].w);
                acc[bi*2+1].x = fmaf(cv[bi], p1.x, acc[bi*2+1].x);
                acc[bi*2+1].y = fmaf(cv[bi], p1.y, acc[bi*2+1].y);
                acc[bi*2+1].z = fmaf(cv[bi], p1.z, acc[bi*2+1].z);
                acc[bi*2+1].w = fmaf(cv[bi], p1.w, acc[bi*2+1].w);
            }
        }

        const int colbase = 8 * g + 4 * og;   // swizzled column offset of row g
        #pragma unroll
        for (int bi = 0; bi < 8; bi++) {
            int b_loc = 8 * o + bi;
            *reinterpret_cast<float4*>(&A_s[b_loc * A_STRIDE + colbase])     = acc[bi*2];
            *reinterpret_cast<float4*>(&A_s[b_loc * A_STRIDE + colbase + 4]) = acc[bi*2+1];
        }
    }
    __syncthreads();

    // ---- Phase 2: one matrix per thread, register Horner, no exchange ----
    const int p = tid;
    const int b = b0 + p;

    // Pull my 8x8 A (16 LDS.128, conflict-free: 68p mod 32 = 4p).
    float A[64];
    #pragma unroll
    for (int r = 0; r < 8; r++) {
        int off = 8 * r + 4 * (r >> 2);       // match the store swizzle
        float4 a0 = *reinterpret_cast<const float4*>(&A_s[p * A_STRIDE + off]);
        float4 a1 = *reinterpret_cast<const float4*>(&A_s[p * A_STRIDE + off + 4]);
        A[8*r+0] = a0.x; A[8*r+1] = a0.y; A[8*r+2] = a0.z; A[8*r+3] = a0.w;
        A[8*r+4] = a1.x; A[8*r+5] = a1.y; A[8*r+6] = a1.z; A[8*r+7] = a1.w;
    }

    // x[b, s*8 .. s*8+8)
    float xv[N_DIM], u[N_DIM];
    {
        const float4* xp = reinterpret_cast<const float4*>(
            x + (size_t)b * (DICT * N_DIM) + s * N_DIM);
        float4 x0 = xp[0], x1 = xp[1];
        xv[0] = x0.x; xv[1] = x0.y; xv[2] = x0.z; xv[3] = x0.w;
        xv[4] = x1.x; xv[5] = x1.y; xv[6] = x1.z; xv[7] = x1.w;
        #pragma unroll
        for (int i = 0; i < N_DIM; i++) u[i] = xv[i];
    }

    // Horner: u <- x + (A u)/k, k = K..1 (rolled; 1/k via constant table).
    #pragma unroll 1
    for (int k = KTERMS; k >= 1; k--) {
        const float ik = INVK[k];
        float t[N_DIM];
        #pragma unroll
        for (int n = 0; n < N_DIM; n++) {
            float sum = A[n * 8 + 0] * u[0];
            #pragma unroll
            for (int j = 1; j < N_DIM; j++)
                sum = fmaf(A[n * 8 + j], u[j], sum);
            t[n] = sum;
        }
        #pragma unroll
        for (int i = 0; i < N_DIM; i++)
            u[i] = fmaf(ik, t[i], xv[i]);
    }

    // Store out[b, s*8 .. s*8+8)
    {
        float4* op = reinterpret_cast<float4*>(
            out + (size_t)b * (DICT * N_DIM) + s * N_DIM);
        op[0] = make_float4(u[0], u[1], u[2], u[3]);
        op[1] = make_float4(u[4], u[5], u[6], u[7]);
    }
}

extern "C" void kernel_launch(void* const* d_in, const int* in_sizes, int n_in,
                              void* d_out, int out_size)
{
    const float* x   = (const float*)d_in[0];  // (8192, 512)
    const float* c   = (const float*)d_in[1];  // (8192, 16)
    const float* psi = (const float*)d_in[2];  // (16, 64, 8, 8)
    float* out = (float*)d_out;                // (8192, 512)

    dim3 grid(B_DIM / NB, DICT);
    transop_expm_kernel<<<grid, BDIM>>>(x, c, psi, out);
}